// round 4
// baseline (speedup 1.0000x reference)
#include <cuda_runtime.h>
#include <cstdint>

// ---------------- configuration ----------------
#define THREADS   512
#define NWARP     (THREADS / 32)        // 16
#define IPT       4                     // items per thread (scatter)
#define TILE      (THREADS * IPT)       // 2048 elements per block
#define NEXP      64
#define MAX_B     1024
#define SCAN_THREADS 1024

// ---------------- scratch (static device globals) ----------------
__device__ unsigned int g_blockHist[NEXP * MAX_B];
__device__ unsigned int g_offsets[NEXP * MAX_B];

// ---------------- kernel 1: per-block expert histogram (int4 loads) -------
__global__ void hist_kernel(const int4* __restrict__ experts4, int total4, int B) {
    __shared__ unsigned int sh[NEXP];
    int t = threadIdx.x;
    if (t < NEXP) sh[t] = 0u;
    __syncthreads();

    // TILE/4 = 512 int4 per block = exactly one per thread
    int i0 = blockIdx.x * (TILE / 4) + t;
    int4 a = (i0 < total4) ? experts4[i0] : make_int4(-1, -1, -1, -1);

    if (i0 < total4) {
        atomicAdd(&sh[a.x], 1u); atomicAdd(&sh[a.y], 1u);
        atomicAdd(&sh[a.z], 1u); atomicAdd(&sh[a.w], 1u);
    }
    __syncthreads();
    if (t < NEXP) g_blockHist[t * B + blockIdx.x] = sh[t];   // expert-major
}

// ---------------- kernel 2: single-block exclusive scan + totals ----------
__device__ __forceinline__ unsigned int warp_incl_scan(unsigned int v) {
    int lane = threadIdx.x & 31;
#pragma unroll
    for (int d = 1; d < 32; d <<= 1) {
        unsigned int n = __shfl_up_sync(0xFFFFFFFFu, v, d);
        if (lane >= d) v += n;
    }
    return v;
}

__global__ void scan_kernel(float* __restrict__ counts_out, int total, int B) {
    const int M = NEXP * B;          // 16384 for B=256
    int t    = threadIdx.x;
    int lane = t & 31;
    int wid  = t >> 5;

    int per   = (M + SCAN_THREADS - 1) / SCAN_THREADS;   // 16
    int start = t * per;
    int end   = start + per; if (end > M) end = M;

    unsigned int sum = 0;
    if ((per & 3) == 0 && start + per <= M) {
        const uint4* p = (const uint4*)&g_blockHist[start];
#pragma unroll 4
        for (int i = 0; i < per / 4; i++) {
            uint4 v = p[i];
            sum += v.x + v.y + v.z + v.w;
        }
    } else {
        for (int i = start; i < end; i++) sum += g_blockHist[i];
    }

    unsigned int incl = warp_incl_scan(sum);
    __shared__ unsigned int wsum[32];
    if (lane == 31) wsum[wid] = incl;
    __syncthreads();
    if (wid == 0) {
        unsigned int w = wsum[lane];
        unsigned int wincl = warp_incl_scan(w);
        wsum[lane] = wincl - w;
    }
    __syncthreads();
    unsigned int run = (incl - sum) + wsum[wid];

    for (int i = start; i < end; i++) {
        unsigned int v = g_blockHist[i];
        g_offsets[i] = run;
        run += v;
    }
    __syncthreads();

    if (t < NEXP) {
        unsigned int s = g_offsets[t * B];
        unsigned int e = (t == NEXP - 1) ? (unsigned int)total : g_offsets[(t + 1) * B];
        counts_out[t] = (float)(e - s);
    }
}

// ---------------- kernel 3: stable scatter, 3 barriers total --------------
__global__ void scatter_kernel(const float* __restrict__ scores,
                               const int* __restrict__ experts,
                               const int* __restrict__ topk_ptr,
                               float* __restrict__ out_scores,
                               float* __restrict__ out_tok,
                               int total, int B) {
    // cnt[(r*NWARP + w)*NEXP + e] : count of expert e in (round r, warp w)
    __shared__ unsigned int cnt[IPT * NWARP * NEXP];   // 4*16*64 = 16 KB
    __shared__ unsigned int sh_off[NEXP];

    const int t    = threadIdx.x;
    const int lane = t & 31;
    const int wid  = t >> 5;
    const int b    = blockIdx.x;

    const int topk = *topk_ptr;
    const bool pow2 = (topk & (topk - 1)) == 0;
    const int shift = pow2 ? (31 - __clz(topk)) : 0;

    if (t < NEXP) sh_off[t] = g_offsets[t * B + b];
#pragma unroll
    for (int i = t; i < IPT * NWARP * NEXP; i += THREADS) cnt[i] = 0u;
    __syncthreads();

    const int base = b * TILE;
    int   e[IPT];
    float sc[IPT];
    int   rk[IPT];

    // Pass 1: load (striped = flat order), warp-local stable ranks, fill cnt.
#pragma unroll
    for (int r = 0; r < IPT; r++) {
        int idx = base + r * THREADS + t;
        bool ok = idx < total;
        e[r]  = ok ? experts[idx] : -1;
        sc[r] = ok ? scores[idx] : 0.0f;

        unsigned int mask = __match_any_sync(0xFFFFFFFFu, e[r]);
        unsigned int lt   = (1u << lane) - 1u;
        rk[r] = __popc(mask & lt);
        int leader = __ffs(mask) - 1;
        if (lane == leader && (unsigned)e[r] < NEXP)
            cnt[(r * NWARP + wid) * NEXP + e[r]] = (unsigned int)__popc(mask);
    }
    __syncthreads();

    // Pass 2: per-expert exclusive scan over 64 (round,warp) slots.
    if (t < NEXP) {
        unsigned int run = 0;
#pragma unroll
        for (int k = 0; k < IPT * NWARP; k++) {
            unsigned int v = cnt[k * NEXP + t];
            cnt[k * NEXP + t] = run;
            run += v;
        }
    }
    __syncthreads();

    // Pass 3: all stores, no further syncs.
#pragma unroll
    for (int r = 0; r < IPT; r++) {
        if ((unsigned)e[r] < NEXP) {
            int idx = base + r * THREADS + t;
            unsigned int pos = sh_off[e[r]]
                             + cnt[(r * NWARP + wid) * NEXP + e[r]]
                             + (unsigned int)rk[r];
            int tok = pow2 ? (idx >> shift) : (idx / topk);
            out_scores[pos] = sc[r];
            out_tok[pos]    = (float)tok;
        }
    }
}

// ---------------- launch ----------------
extern "C" void kernel_launch(void* const* d_in, const int* in_sizes, int n_in,
                              void* d_out, int out_size) {
    const float* scores   = (const float*)d_in[0];
    const int*   experts  = (const int*)  d_in[1];
    const int*   topk_ptr = (const int*)  d_in[3];

    int total = in_sizes[0];                        // 524288
    int B = (total + TILE - 1) / TILE;              // 256
    if (B > MAX_B) B = MAX_B;

    float* out        = (float*)d_out;
    float* out_scores = out;
    float* out_tok    = out + total;
    float* out_counts = out + 2 * (size_t)total;

    hist_kernel<<<B, THREADS>>>((const int4*)experts, total / 4, B);
    scan_kernel<<<1, SCAN_THREADS>>>(out_counts, total, B);
    scatter_kernel<<<B, THREADS>>>(scores, experts, topk_ptr,
                                   out_scores, out_tok, total, B);
}

// round 7
// speedup vs baseline: 1.3776x; 1.3776x over previous
#include <cuda_runtime.h>
#include <cstdint>

// ---------------- configuration ----------------
#define THREADS   512
#define NWARP     (THREADS / 32)        // 16
#define IPT       8                     // items per thread
#define TILE      (THREADS * IPT)       // 4096 elements per block
#define NEXP      64
#define MAXB      296                   // co-residency bound (instance: B=128)
#define NSLOT     (IPT * NWARP)         // 128 (round,warp) slots
#define NCHUNK    8                     // chunks; NSLOT/NCHUNK = 16 slots each

// ---------------- scratch (static device globals) ----------------
__device__ unsigned int g_blockHist[NEXP * MAXB];
__device__ unsigned int g_rowPref [NEXP * MAXB];
__device__ unsigned int g_expTotal[NEXP];
__device__ unsigned int g_count = 0;
__device__ unsigned int g_gen   = 0;

// sense-reversing grid barrier; resets g_count each use -> graph-replay safe
__device__ __forceinline__ void grid_barrier(int nblocks) {
    __syncthreads();
    if (threadIdx.x == 0) {
        __threadfence();
        unsigned gen = *((volatile unsigned int*)&g_gen);
        if (atomicAdd(&g_count, 1u) == (unsigned)(nblocks - 1)) {
            g_count = 0u;
            __threadfence();
            *((volatile unsigned int*)&g_gen) = gen + 1u;
        } else {
            while (*((volatile unsigned int*)&g_gen) == gen) {
                __nanosleep(64);
            }
            __threadfence();
        }
    }
    __syncthreads();
}

__device__ __forceinline__ unsigned int warp_incl_scan(unsigned int v) {
    int lane = threadIdx.x & 31;
#pragma unroll
    for (int d = 1; d < 32; d <<= 1) {
        unsigned int n = __shfl_up_sync(0xFFFFFFFFu, v, d);
        if (lane >= d) v += n;
    }
    return v;
}

__global__ void __launch_bounds__(THREADS, 2)
fused_kernel(const float* __restrict__ scores,
             const int*   __restrict__ experts,
             const int*   __restrict__ topk_ptr,
             float* __restrict__ out_scores,
             float* __restrict__ out_tok,
             float* __restrict__ out_counts,
             int total, int B) {
    // cnt[k*NEXP + e], k = r*NWARP + w : count of expert e in (round r, warp w)
    __shared__ unsigned int cnt [NSLOT * NEXP];    // 32 KB
    __shared__ unsigned int sums[NCHUNK * NEXP];   // 2 KB chunk sums
    __shared__ unsigned int sh_off[NEXP];
    __shared__ unsigned int s_w[NWARP];

    const int t    = threadIdx.x;
    const int lane = t & 31;
    const int wid  = t >> 5;
    const int b    = blockIdx.x;

    const int topk  = *topk_ptr;
    const bool pow2 = (topk & (topk - 1)) == 0;
    const int shift = pow2 ? (31 - __clz(topk)) : 0;

#pragma unroll
    for (int i = t; i < NSLOT * NEXP; i += THREADS) cnt[i] = 0u;
    __syncthreads();

    // ---------------- Phase A: load + warp ranks + block-local counts -----
    const int base = b * TILE;
    int   e[IPT];
    float sc[IPT];
    int   rk[IPT];

#pragma unroll
    for (int r = 0; r < IPT; r++) {
        int idx = base + r * THREADS + t;            // striped = flat order
        bool ok = idx < total;
        e[r]  = ok ? experts[idx] : -1;
        sc[r] = ok ? scores[idx] : 0.0f;

        unsigned int mask = __match_any_sync(0xFFFFFFFFu, e[r]);
        rk[r] = __popc(mask & ((1u << lane) - 1u));
        if (lane == (__ffs(mask) - 1) && (unsigned)e[r] < NEXP)
            cnt[(r * NWARP + wid) * NEXP + e[r]] = (unsigned int)__popc(mask);
    }
    __syncthreads();

    // hierarchical per-expert scan of cnt along k (bank-conflict-free):
    {
        int c = t >> 6, ee = t & 63;
        unsigned int s = 0;
#pragma unroll
        for (int i = 0; i < NSLOT / NCHUNK; i++)
            s += cnt[(c * (NSLOT / NCHUNK) + i) * NEXP + ee];
        sums[c * NEXP + ee] = s;
    }
    __syncthreads();
    // scan chunk sums per expert; total = per-block histogram -> global
    if (t < NEXP) {
        unsigned int run = 0;
#pragma unroll
        for (int c = 0; c < NCHUNK; c++) {
            unsigned int v = sums[c * NEXP + t];
            sums[c * NEXP + t] = run;
            run += v;
        }
        g_blockHist[t * B + b] = run;                // expert-major
    }
    __syncthreads();
    // rewrite cnt with exclusive prefixes
    {
        int c = t >> 6, ee = t & 63;
        unsigned int run = sums[c * NEXP + ee];
#pragma unroll
        for (int i = 0; i < NSLOT / NCHUNK; i++) {
            int k = c * (NSLOT / NCHUNK) + i;
            unsigned int v = cnt[k * NEXP + ee];
            cnt[k * NEXP + ee] = run;
            run += v;
        }
    }

    grid_barrier(B);

    // ---------------- Phase B: blocks 0..63 scan their expert's row -------
    unsigned int v = 0, incl = 0;
    if (b < NEXP && t < 128) {
        v = (t < B) ? g_blockHist[b * B + t] : 0u;
        incl = warp_incl_scan(v);
        if (lane == 31) s_w[wid] = incl;
    }
    __syncthreads();
    if (b < NEXP && t < 128) {
        unsigned int wofs = 0;
#pragma unroll
        for (int w = 0; w < 4; w++) if (w < wid) wofs += s_w[w];
        unsigned int excl = incl - v + wofs;
        if (t < B) g_rowPref[b * B + t] = excl;
        if (t == 127) g_expTotal[b] = excl + v;
    }

    grid_barrier(B);

    // ---------------- Phase C: expert bases + scatter ---------------------
    unsigned int tot = 0, incl2 = 0;
    if (t < NEXP) {
        tot   = g_expTotal[t];
        incl2 = warp_incl_scan(tot);
        if (t == 31) s_w[8] = incl2;   // warp0 total, consumed by warp1
    }
    __syncthreads();
    if (t < NEXP) {
        unsigned int ebase = incl2 - tot + ((t >= 32) ? s_w[8] : 0u);
        sh_off[t] = ebase + g_rowPref[t * B + b];
        if (b == 0) out_counts[t] = (float)tot;
    }
    __syncthreads();

#pragma unroll
    for (int r = 0; r < IPT; r++) {
        if ((unsigned)e[r] < NEXP) {
            int idx = base + r * THREADS + t;
            unsigned int pos = sh_off[e[r]]
                             + cnt[(r * NWARP + wid) * NEXP + e[r]]
                             + (unsigned int)rk[r];
            int tok = pow2 ? (idx >> shift) : (idx / topk);
            out_scores[pos] = sc[r];
            out_tok[pos]    = (float)tok;
        }
    }
}

// ---------------- launch ----------------
extern "C" void kernel_launch(void* const* d_in, const int* in_sizes, int n_in,
                              void* d_out, int out_size) {
    const float* scores   = (const float*)d_in[0];
    const int*   experts  = (const int*)  d_in[1];
    const int*   topk_ptr = (const int*)  d_in[3];

    int total = in_sizes[0];                        // 524288
    int B = (total + TILE - 1) / TILE;              // 128
    if (B > MAXB) B = MAXB;                         // (instance fits; all co-resident)

    float* out        = (float*)d_out;
    float* out_scores = out;                        // [0, total)
    float* out_tok    = out + total;                // [total, 2*total)
    float* out_counts = out + 2 * (size_t)total;    // [2*total, +64)

    fused_kernel<<<B, THREADS>>>(scores, experts, topk_ptr,
                                 out_scores, out_tok, out_counts,
                                 total, B);
}

// round 12
// speedup vs baseline: 1.9698x; 1.4298x over previous
#include <cuda_runtime.h>
#include <cstdint>

// ---------------- configuration ----------------
#define THREADS   1024
#define NWARP     (THREADS / 32)        // 32
#define IPT       4                     // items per thread
#define TILE      (THREADS * IPT)       // 4096 elements per block
#define NEXP      64
#define MAXB      296
#define NSLOT     (IPT * NWARP)         // 128 (round,warp) slots
#define NCHUNK    16                    // chunks; NSLOT/NCHUNK = 8 slots each

// ---------------- scratch (static device globals) ----------------
__device__ unsigned int g_blockHist[NEXP * MAXB];
__device__ unsigned int g_count = 0;
__device__ unsigned int g_gen   = 0;

// sense-reversing grid barrier; resets g_count each use -> graph-replay safe
__device__ __forceinline__ void grid_barrier(int nblocks) {
    __syncthreads();
    if (threadIdx.x == 0) {
        __threadfence();
        unsigned gen = *((volatile unsigned int*)&g_gen);
        if (atomicAdd(&g_count, 1u) == (unsigned)(nblocks - 1)) {
            g_count = 0u;
            __threadfence();
            *((volatile unsigned int*)&g_gen) = gen + 1u;
        } else {
            while (*((volatile unsigned int*)&g_gen) == gen) __nanosleep(64);
            __threadfence();
        }
    }
    __syncthreads();
}

__device__ __forceinline__ unsigned int warp_incl_scan(unsigned int v) {
    int lane = threadIdx.x & 31;
#pragma unroll
    for (int d = 1; d < 32; d <<= 1) {
        unsigned int n = __shfl_up_sync(0xFFFFFFFFu, v, d);
        if (lane >= d) v += n;
    }
    return v;
}

__global__ void __launch_bounds__(THREADS, 1)
fused_kernel(const float* __restrict__ scores,
             const int*   __restrict__ experts,
             const int*   __restrict__ topk_ptr,
             float* __restrict__ out_scores,
             float* __restrict__ out_tok,
             float* __restrict__ out_counts,
             int total, int B) {
    // all counts/prefixes are <= TILE=4096 -> fit in u16
    __shared__ uint16_t     cnt16 [NSLOT * NEXP];   // 16 KB
    __shared__ uint16_t     sums16[NCHUNK * NEXP];  // 2 KB
    __shared__ unsigned int s_pk  [TILE];           // 16 KB: (e<<12)|j_orig
    __shared__ unsigned int tot_l [NEXP];
    __shared__ unsigned int ebl   [NEXP];           // block-local expert base
    __shared__ unsigned int sh_off[NEXP];           // global base of this block's run
    __shared__ unsigned int s_pre [NEXP];
    __shared__ unsigned int s_w[2];

    const int t    = threadIdx.x;
    const int lane = t & 31;
    const int wid  = t >> 5;
    const int b    = blockIdx.x;

    const int topk  = *topk_ptr;
    const bool pow2 = (topk & (topk - 1)) == 0;
    const int shift = pow2 ? (31 - __clz(topk)) : 0;

    // zero count matrix (u32-wide)
#pragma unroll
    for (int i = t; i < NSLOT * NEXP / 2; i += THREADS)
        ((unsigned int*)cnt16)[i] = 0u;
    __syncthreads();

    // ---------------- Phase A: load experts + warp ranks + count matrix ---
    const int base = b * TILE;
    int e[IPT];
    int rk[IPT];

#pragma unroll
    for (int r = 0; r < IPT; r++) {
        int idx = base + r * THREADS + t;            // striped = flat order
        e[r] = (idx < total) ? experts[idx] : -1;
        unsigned int mask = __match_any_sync(0xFFFFFFFFu, e[r]);
        rk[r] = __popc(mask & ((1u << lane) - 1u));
        if (lane == (__ffs(mask) - 1) && (unsigned)e[r] < NEXP)
            cnt16[(r * NWARP + wid) * NEXP + e[r]] = (uint16_t)__popc(mask);
    }
    __syncthreads();

    // chunk sums over slots per expert
    {
        int c = t >> 6, ee = t & 63;
        unsigned int s = 0;
#pragma unroll
        for (int i = 0; i < NSLOT / NCHUNK; i++)
            s += cnt16[(c * (NSLOT / NCHUNK) + i) * NEXP + ee];
        sums16[c * NEXP + ee] = (uint16_t)s;
    }
    __syncthreads();
    // scan chunk sums per expert -> block histogram
    if (t < NEXP) {
        unsigned int run = 0;
#pragma unroll
        for (int c = 0; c < NCHUNK; c++) {
            unsigned int v = sums16[c * NEXP + t];
            sums16[c * NEXP + t] = (uint16_t)run;
            run += v;
        }
        g_blockHist[t * B + b] = run;                // expert-major
        tot_l[t] = run;
    }
    __syncthreads();
    // rewrite cnt with within-expert exclusive prefixes
    {
        int c = t >> 6, ee = t & 63;
        unsigned int run = sums16[c * NEXP + ee];
#pragma unroll
        for (int i = 0; i < NSLOT / NCHUNK; i++) {
            int k = c * (NSLOT / NCHUNK) + i;
            unsigned int v = cnt16[k * NEXP + ee];
            cnt16[k * NEXP + ee] = (uint16_t)run;
            run += v;
        }
    }
    // block-local expert bases (exclusive scan over 64 totals, 2 warps)
    unsigned int vv = 0, inc = 0;
    if (t < NEXP) {
        vv = tot_l[t];
        inc = warp_incl_scan(vv);
        if (t == 31) s_w[0] = inc;
    }
    __syncthreads();
    if (t < NEXP) ebl[t] = inc - vv + ((t >= 32) ? s_w[0] : 0u);
    __syncthreads();

    // local counting sort of keys into smem (block-sorted by expert, stable)
#pragma unroll
    for (int r = 0; r < IPT; r++) {
        if ((unsigned)e[r] < NEXP) {
            int jo = r * THREADS + t;                // orig position in tile
            unsigned int pl = ebl[e[r]]
                            + cnt16[(r * NWARP + wid) * NEXP + e[r]]
                            + (unsigned int)rk[r];
            s_pk[pl] = ((unsigned int)e[r] << 12) | (unsigned int)jo;
        }
    }

    grid_barrier(B);

    // ---------------- Phase C: global bases from full hist matrix ---------
    // 16 threads per expert: ee = t>>4, sub = t&15
    {
        int ee = t >> 4, sub = t & 15;
        unsigned int tot = 0, pre = 0;
        for (int b2 = sub; b2 < B; b2 += 16) {
            unsigned int v = g_blockHist[ee * B + b2];
            tot += v;
            if (b2 < b) pre += v;
        }
#pragma unroll
        for (int d = 1; d < 16; d <<= 1) {
            tot += __shfl_xor_sync(0xFFFFFFFFu, tot, d);
            pre += __shfl_xor_sync(0xFFFFFFFFu, pre, d);
        }
        if (sub == 0) { tot_l[ee] = tot; s_pre[ee] = pre; }
    }
    __syncthreads();
    unsigned int tv = 0, ti = 0;
    if (t < NEXP) {
        tv = tot_l[t];
        ti = warp_incl_scan(tv);
        if (t == 31) s_w[1] = ti;
    }
    __syncthreads();
    if (t < NEXP) {
        unsigned int ebase = ti - tv + ((t >= 32) ? s_w[1] : 0u);
        sh_off[t] = ebase + s_pre[t];
        if (b == 0) out_counts[t] = (float)tv;
    }
    __syncthreads();

    // ---------------- write-out: coalesced stores + local score gather ----
    const int valid = min(TILE, total - base);
#pragma unroll
    for (int r = 0; r < IPT; r++) {
        int j = r * THREADS + t;                     // sorted position
        if (j < valid) {
            unsigned int pk = s_pk[j];
            unsigned int ee = pk >> 12;
            int jo  = (int)(pk & 0x0FFFu);
            int idx = base + jo;
            unsigned int dst = sh_off[ee] + (unsigned int)j - ebl[ee];
            int tok = pow2 ? (idx >> shift) : (idx / topk);
            out_scores[dst] = scores[idx];           // gather within own 16KB tile (L1)
            out_tok[dst]    = (float)tok;
        }
    }
}

// ---------------- launch ----------------
extern "C" void kernel_launch(void* const* d_in, const int* in_sizes, int n_in,
                              void* d_out, int out_size) {
    const float* scores   = (const float*)d_in[0];
    const int*   experts  = (const int*)  d_in[1];
    const int*   topk_ptr = (const int*)  d_in[3];

    int total = in_sizes[0];                        // 524288
    int B = (total + TILE - 1) / TILE;              // 128
    if (B > MAXB) B = MAXB;                         // all blocks co-resident

    float* out        = (float*)d_out;
    float* out_scores = out;                        // [0, total)
    float* out_tok    = out + total;                // [total, 2*total)
    float* out_counts = out + 2 * (size_t)total;    // [2*total, +64)

    fused_kernel<<<B, THREADS>>>(scores, experts, topk_ptr,
                                 out_scores, out_tok, out_counts,
                                 total, B);
}